// round 13
// baseline (speedup 1.0000x reference)
#include <cuda_runtime.h>
#include <cuda_fp16.h>
#include <math.h>

#define NB 8192
#define BB 64
#define DD 5
#define NE (NB*DD)      // 40960 neighbor edges
#define NT (NB*BB)      // 524288 (node, batch) rows
#define HC 16

typedef unsigned long long u64;

// ---------------- packed f32x2 helpers (sm_103a) ----------------------------
__device__ __forceinline__ u64 pk2(float lo, float hi) {
    u64 r; asm("mov.b64 %0, {%1, %2};" : "=l"(r) : "f"(lo), "f"(hi)); return r;
}
__device__ __forceinline__ void up2(u64 v, float& lo, float& hi) {
    asm("mov.b64 {%0, %1}, %2;" : "=f"(lo), "=f"(hi) : "l"(v));
}
__device__ __forceinline__ u64 add2(u64 a, u64 b) {
    u64 r; asm("add.rn.f32x2 %0, %1, %2;" : "=l"(r) : "l"(a), "l"(b)); return r;
}
__device__ __forceinline__ u64 mul2(u64 a, u64 b) {
    u64 r; asm("mul.rn.f32x2 %0, %1, %2;" : "=l"(r) : "l"(a), "l"(b)); return r;
}
__device__ __forceinline__ u64 fma2(u64 a, u64 b, u64 c) {
    u64 r; asm("fma.rn.f32x2 %0, %1, %2, %3;" : "=l"(r) : "l"(a), "l"(b), "l"(c)); return r;
}
__device__ __forceinline__ u64 h2_to_f2(unsigned h) {
    float2 f = __half22float2(*reinterpret_cast<__half2*>(&h));
    return pk2(f.x, f.y);
}

// ---------------- device scratch (no runtime allocation allowed) ------------
__device__ __half g_xlA[(size_t)NT * HC];   // 16.8 MB, layout (n,b,hc) fp16
__device__ __half g_xrA[(size_t)NT * HC];
__device__ __half g_xlB[(size_t)NT * HC];
__device__ __half g_xrB[(size_t)NT * HC];
__device__ float  g_h  [(size_t)NT * HC];   // final-layer h only (fp32)
__device__ float  g_pool[BB * HC];          // pooled sums (REDG in last layer)
__device__ int    g_cnt[NB];                // static zero-init; scan re-zeroes
__device__ int    g_off[NB + 1];
__device__ int    g_cur[NB];
__device__ int    g_csr[NE];

// ---------------- fp16 quarter-row <-> fp32 helpers ------------------------
__device__ __forceinline__ uint2 q_f2h(float4 v) {
    __half2 h0 = __floats2half2_rn(v.x, v.y);
    __half2 h1 = __floats2half2_rn(v.z, v.w);
    uint2 u;
    u.x = *reinterpret_cast<unsigned*>(&h0);
    u.y = *reinterpret_cast<unsigned*>(&h1);
    return u;
}

// ---------------- CSR scan (re-zeroes counts for next graph replay) --------
__global__ void scan_kernel() {
    __shared__ int wsum[32];
    int t = threadIdx.x;
    int v[8];
    int s = 0;
#pragma unroll
    for (int i = 0; i < 8; i++) {
        v[i] = g_cnt[t * 8 + i];
        g_cnt[t * 8 + i] = 0;          // reset for next replay
        s += v[i];
    }
    unsigned lane = t & 31, wid = t >> 5;
    int x = s;
#pragma unroll
    for (int o = 1; o < 32; o <<= 1) {
        int y = __shfl_up_sync(0xffffffffu, x, o);
        if (lane >= (unsigned)o) x += y;
    }
    if (lane == 31) wsum[wid] = x;
    __syncthreads();
    if (wid == 0) {
        int w = wsum[lane];
#pragma unroll
        for (int o = 1; o < 32; o <<= 1) {
            int y = __shfl_up_sync(0xffffffffu, w, o);
            if (lane >= (unsigned)o) w += y;
        }
        wsum[lane] = w;
    }
    __syncthreads();
    int excl = x - s + (wid ? wsum[wid - 1] : 0);
    int run = excl;
#pragma unroll
    for (int i = 0; i < 8; i++) {
        g_off[t * 8 + i] = run;
        g_cur[t * 8 + i] = run;
        run += v[i];
    }
    if (t == 1023) g_off[NB] = run;
}

__global__ void fill_kernel(const int* __restrict__ neighbors) {
    int e = blockIdx.x * blockDim.x + threadIdx.x;
    if (e < NE) {
        int dst = neighbors[e];
        int pos = atomicAdd(&g_cur[dst], 1);
        g_csr[pos] = e / DD;   // source node of edge e
    }
}

// ---------------- layer-0 projections (quad-sliced, coalesced, fp16 out) ---
__global__ __launch_bounds__(256)
void proj0_kernel(const float* __restrict__ xin,
                  const float* __restrict__ neighbors_i,
                  const float* __restrict__ Wl, const float* __restrict__ Wr) {
    __shared__ float sWl[256], sWr[256];
    int t = threadIdx.x;
    sWl[t] = Wl[t];
    sWr[t] = Wr[t];

    // fused CSR count + pool-accumulator zeroing (replay-safe)
    int e = blockIdx.x * 256 + t;
    if (e < NE) atomicAdd(&g_cnt[((const int*)neighbors_i)[e]], 1);
    if (blockIdx.x == 0) {
#pragma unroll
        for (int i = 0; i < (BB * HC) / 256; i++) g_pool[t + i * 256] = 0.f;
    }
    __syncthreads();

    int row = blockIdx.x * 64 + (t >> 2);   // row = n*64 + b
    int hq  = t & 3;
    int n = row >> 6, b = row & 63;

    float4 xq = __ldcs((const float4*)(xin + ((size_t)b * NB + n) * HC) + hq);

    float4 ol  = make_float4(0.f, 0.f, 0.f, 0.f);
    float4 orr = ol;
    int qbase = (t & 31) & ~3;
#pragma unroll
    for (int f = 0; f < 16; f++) {
        float src = (f & 3) == 0 ? xq.x : (f & 3) == 1 ? xq.y
                  : (f & 3) == 2 ? xq.z : xq.w;
        float hf = __shfl_sync(0xffffffffu, src, qbase | (f >> 2), 32);
        float4 wl = *(const float4*)&sWl[f * 16 + hq * 4];
        float4 wr = *(const float4*)&sWr[f * 16 + hq * 4];
        ol.x  = fmaf(hf, wl.x, ol.x);  ol.y  = fmaf(hf, wl.y, ol.y);
        ol.z  = fmaf(hf, wl.z, ol.z);  ol.w  = fmaf(hf, wl.w, ol.w);
        orr.x = fmaf(hf, wr.x, orr.x); orr.y = fmaf(hf, wr.y, orr.y);
        orr.z = fmaf(hf, wr.z, orr.z); orr.w = fmaf(hf, wr.w, orr.w);
    }
    ((uint2*)(g_xlA + (size_t)row * HC))[hq] = q_f2h(ol);
    ((uint2*)(g_xrA + (size_t)row * HC))[hq] = q_f2h(orr);
}

// ---------------- fused GATv2 layer: 2 rows/thread, f32x2, fp16 buffers ----
// Block = one node n, 128 threads = 32 batch-pairs x 4 head-quarters.
// Thread (b0 = t>>2, hq = t&3) handles batches b0 and b0+32.
// leaky_relu(z, 0.2) = 0.6*z + 0.4*|z|, plain-exp softmax via exp2
// (log2e folded into attention weights). LAST layer also REDG-accumulates
// the node-mean pool sums into g_pool.
template <int IN, bool LAST>
__global__ __launch_bounds__(128)
void gat4_kernel(const float* __restrict__ attw,
                 const float* __restrict__ bias,
                 const float* __restrict__ Wln,   // next layer's Wl (null if LAST)
                 const float* __restrict__ Wrn) { // next layer's Wr (null if LAST)
    __shared__ float sWl[256], sWr[256];
    int t = threadIdx.x;
    if (!LAST) {
        sWl[t] = Wln[t]; sWl[t + 128] = Wln[t + 128];
        sWr[t] = Wrn[t]; sWr[t + 128] = Wrn[t + 128];
        __syncthreads();
    }

    const __half* __restrict__ xlin  = (IN == 0) ? g_xlA : g_xlB;
    const __half* __restrict__ xrin  = (IN == 0) ? g_xrA : g_xrB;
    __half*       __restrict__ xlout = (IN == 0) ? g_xlB : g_xlA;
    __half*       __restrict__ xrout = (IN == 0) ? g_xrB : g_xrA;

    int n  = blockIdx.x;
    int b0 = t >> 2;           // 0..31
    int hq = t & 3;
    size_t idx0 = (size_t)n * BB + b0;     // row A
    size_t idx1 = idx0 + 32;               // row B (b0+32)

    const float LOG2E = 1.4426950408889634f;
    float4 att4 = __ldg((const float4*)attw + hq);
    u64 aw01 = pk2(att4.x * LOG2E, att4.y * LOG2E);
    u64 aw23 = pk2(att4.z * LOG2E, att4.w * LOG2E);
    const u64 ABSM = 0x7fffffff7fffffffULL;
    u64 c06 = pk2(0.6f, 0.6f), c04 = pk2(0.4f, 0.4f);

    uint2 xruA = ((const uint2*)(xrin + idx0 * HC))[hq];
    uint2 xruB = ((const uint2*)(xrin + idx1 * HC))[hq];
    u64 xrA01 = h2_to_f2(xruA.x), xrA23 = h2_to_f2(xruA.y);
    u64 xrB01 = h2_to_f2(xruB.x), xrB23 = h2_to_f2(xruB.y);

    // ---- self edges -------------------------------------------------------
    float sA, sB;
    u64 accA01, accA23, accB01, accB23;
    {
        uint2 su = ((const uint2*)(xlin + idx0 * HC))[hq];
        u64 Q01 = h2_to_f2(su.x), Q23 = h2_to_f2(su.y);
        u64 z01 = add2(Q01, xrA01), z23 = add2(Q23, xrA23);
        u64 lk01 = fma2(z01 & ABSM, c04, mul2(z01, c06));
        u64 lk23 = fma2(z23 & ABSM, c04, mul2(z23, c06));
        u64 l2 = fma2(lk23, aw23, mul2(lk01, aw01));
        float lx, ly; up2(l2, lx, ly);
        float w = exp2f(lx + ly);
        sA = w;
        u64 wp = pk2(w, w);
        accA01 = mul2(wp, Q01);
        accA23 = mul2(wp, Q23);
    }
    {
        uint2 su = ((const uint2*)(xlin + idx1 * HC))[hq];
        u64 Q01 = h2_to_f2(su.x), Q23 = h2_to_f2(su.y);
        u64 z01 = add2(Q01, xrB01), z23 = add2(Q23, xrB23);
        u64 lk01 = fma2(z01 & ABSM, c04, mul2(z01, c06));
        u64 lk23 = fma2(z23 & ABSM, c04, mul2(z23, c06));
        u64 l2 = fma2(lk23, aw23, mul2(lk01, aw01));
        float lx, ly; up2(l2, lx, ly);
        float w = exp2f(lx + ly);
        sB = w;
        u64 wp = pk2(w, w);
        accB01 = mul2(wp, Q01);
        accB23 = mul2(wp, Q23);
    }

    // ---- incoming-edge loop, both rows, 2-deep prefetch -------------------
    int beg = __ldg(&g_off[n]), end = __ldg(&g_off[n + 1]);
    int offA = b0 * HC + hq * 4;           // half units
    int offB = offA + 32 * HC;
    uint2 PA0 = make_uint2(0u, 0u), PB0 = PA0, PA1 = PA0, PB1 = PA0;
    if (beg < end) {
        const __half* p = xlin + (size_t)__ldg(&g_csr[beg]) * (BB * HC);
        PA0 = *(const uint2*)(p + offA);
        PB0 = *(const uint2*)(p + offB);
    }
    if (beg + 1 < end) {
        const __half* p = xlin + (size_t)__ldg(&g_csr[beg + 1]) * (BB * HC);
        PA1 = *(const uint2*)(p + offA);
        PB1 = *(const uint2*)(p + offB);
    }
    for (int e = beg; e < end; e++) {
        u64 QA01 = h2_to_f2(PA0.x), QA23 = h2_to_f2(PA0.y);
        u64 QB01 = h2_to_f2(PB0.x), QB23 = h2_to_f2(PB0.y);
        PA0 = PA1; PB0 = PB1;
        if (e + 2 < end) {
            const __half* p = xlin + (size_t)__ldg(&g_csr[e + 2]) * (BB * HC);
            PA1 = *(const uint2*)(p + offA);
            PB1 = *(const uint2*)(p + offB);
        }
        // row A
        u64 z01 = add2(QA01, xrA01), z23 = add2(QA23, xrA23);
        u64 lk01 = fma2(z01 & ABSM, c04, mul2(z01, c06));
        u64 lk23 = fma2(z23 & ABSM, c04, mul2(z23, c06));
        u64 l2 = fma2(lk23, aw23, mul2(lk01, aw01));
        float lx, ly; up2(l2, lx, ly);
        float wA = exp2f(lx + ly);
        sA += wA;
        u64 wp = pk2(wA, wA);
        accA01 = fma2(wp, QA01, accA01);
        accA23 = fma2(wp, QA23, accA23);
        // row B
        z01 = add2(QB01, xrB01); z23 = add2(QB23, xrB23);
        lk01 = fma2(z01 & ABSM, c04, mul2(z01, c06));
        lk23 = fma2(z23 & ABSM, c04, mul2(z23, c06));
        l2 = fma2(lk23, aw23, mul2(lk01, aw01));
        up2(l2, lx, ly);
        float wB = exp2f(lx + ly);
        sB += wB;
        wp = pk2(wB, wB);
        accB01 = fma2(wp, QB01, accB01);
        accB23 = fma2(wp, QB23, accB23);
    }

    // ---- finalize both new h quarters -------------------------------------
    float4 bb4 = __ldg((const float4*)bias + hq);
    u64 bb01 = pk2(bb4.x, bb4.y), bb23 = pk2(bb4.z, bb4.w);
    float invA = 1.f / (sA + 1e-16f);
    float invB = 1.f / (sB + 1e-16f);
    u64 ipA = pk2(invA, invA), ipB = pk2(invB, invB);
    float4 oA, oB;
    {
        u64 o01 = fma2(accA01, ipA, bb01), o23 = fma2(accA23, ipA, bb23);
        up2(o01, oA.x, oA.y); up2(o23, oA.z, oA.w);
        o01 = fma2(accB01, ipB, bb01); o23 = fma2(accB23, ipB, bb23);
        up2(o01, oB.x, oB.y); up2(o23, oB.z, oB.w);
    }

    if (LAST) {
        ((float4*)(g_h + idx0 * HC))[hq] = oA;
        ((float4*)(g_h + idx1 * HC))[hq] = oB;
        // fused pool accumulation (REDG, no-return)
        int pA = b0 * HC + hq * 4;
        int pB = pA + 32 * HC;
        atomicAdd(&g_pool[pA + 0], oA.x);
        atomicAdd(&g_pool[pA + 1], oA.y);
        atomicAdd(&g_pool[pA + 2], oA.z);
        atomicAdd(&g_pool[pA + 3], oA.w);
        atomicAdd(&g_pool[pB + 0], oB.x);
        atomicAdd(&g_pool[pB + 1], oB.y);
        atomicAdd(&g_pool[pB + 2], oB.z);
        atomicAdd(&g_pool[pB + 3], oB.w);
        return;
    }

    // ---- next-layer projections: quad shuffle, f32x2, weights shared ------
    u64 olA01 = 0, olA23 = 0, orA01 = 0, orA23 = 0;
    u64 olB01 = 0, olB23 = 0, orB01 = 0, orB23 = 0;
    int qbase = (t & 31) & ~3;
#pragma unroll
    for (int f = 0; f < 16; f++) {
        float srcA = (f & 3) == 0 ? oA.x : (f & 3) == 1 ? oA.y
                   : (f & 3) == 2 ? oA.z : oA.w;
        float srcB = (f & 3) == 0 ? oB.x : (f & 3) == 1 ? oB.y
                   : (f & 3) == 2 ? oB.z : oB.w;
        float hfA = __shfl_sync(0xffffffffu, srcA, qbase | (f >> 2), 32);
        float hfB = __shfl_sync(0xffffffffu, srcB, qbase | (f >> 2), 32);
        u64 hpA = pk2(hfA, hfA), hpB = pk2(hfB, hfB);
        u64 wl01 = *(const u64*)&sWl[f * 16 + hq * 4];
        u64 wl23 = *(const u64*)&sWl[f * 16 + hq * 4 + 2];
        u64 wr01 = *(const u64*)&sWr[f * 16 + hq * 4];
        u64 wr23 = *(const u64*)&sWr[f * 16 + hq * 4 + 2];
        olA01 = fma2(hpA, wl01, olA01); olA23 = fma2(hpA, wl23, olA23);
        orA01 = fma2(hpA, wr01, orA01); orA23 = fma2(hpA, wr23, orA23);
        olB01 = fma2(hpB, wl01, olB01); olB23 = fma2(hpB, wl23, olB23);
        orB01 = fma2(hpB, wr01, orB01); orB23 = fma2(hpB, wr23, orB23);
    }
    float4 v;
    up2(olA01, v.x, v.y); up2(olA23, v.z, v.w);
    ((uint2*)(xlout + idx0 * HC))[hq] = q_f2h(v);
    up2(orA01, v.x, v.y); up2(orA23, v.z, v.w);
    ((uint2*)(xrout + idx0 * HC))[hq] = q_f2h(v);
    up2(olB01, v.x, v.y); up2(olB23, v.z, v.w);
    ((uint2*)(xlout + idx1 * HC))[hq] = q_f2h(v);
    up2(orB01, v.x, v.y); up2(orB23, v.z, v.w);
    ((uint2*)(xrout + idx1 * HC))[hq] = q_f2h(v);
}

// ---------------- agg MLP + edge scorer, one block per batch ---------------
__global__ __launch_bounds__(128)
void pool2_scorer_kernel(const int* __restrict__ agent_nodes,
                         const int* __restrict__ neighbors,
                         const float* __restrict__ Wg1, const float* __restrict__ bg1,
                         const float* __restrict__ Wg2, const float* __restrict__ bg2,
                         const float* __restrict__ We1, const float* __restrict__ be1,
                         const float* __restrict__ We2, const float* __restrict__ be2,
                         const float* __restrict__ We3, const float* __restrict__ be3,
                         float* __restrict__ out) {
    int b = blockIdx.x;
    int t = threadIdx.x;   // 128 threads
    __shared__ float pool[16], g1[32], agg[64];
    if (t < 16) pool[t] = g_pool[b * 16 + t] * (1.f / (float)NB);
    __syncthreads();
    if (t < 32) {
        float s = bg1[t];
#pragma unroll
        for (int ff = 0; ff < 16; ff++) s = fmaf(pool[ff], Wg1[ff * 32 + t], s);
        g1[t] = tanhf(s);
    }
    __syncthreads();
    if (t < 64) {
        float s = bg2[t];
#pragma unroll
        for (int k = 0; k < 32; k++) s = fmaf(g1[k], Wg2[k * 64 + t], s);
        agg[t] = tanhf(s);
    }
    __syncthreads();

    if (t >= 3 * DD) return;          // 15 scorer items per batch
    int tk = t / DD;
    int d  = t % DD;
    int an = agent_nodes[b];
    int tg = neighbors[an * DD + d];

    float acc1[16];
#pragma unroll
    for (int o = 0; o < 16; o++) acc1[o] = be1[o];

#pragma unroll
    for (int ff = 0; ff < 16; ff++) {                       // source [0,16)
        float val = g_h[((size_t)an * BB + b) * HC + ff];
#pragma unroll
        for (int o = 0; o < 16; o++) acc1[o] = fmaf(val, We1[ff * 16 + o], acc1[o]);
    }
    {                                                       // token one-hot [16,19)
        int i = 16 + tk;
#pragma unroll
        for (int o = 0; o < 16; o++) acc1[o] += We1[i * 16 + o];
    }
#pragma unroll
    for (int ff = 0; ff < 16; ff++) {                       // target [19,35)
        float val = g_h[((size_t)tg * BB + b) * HC + ff];
#pragma unroll
        for (int o = 0; o < 16; o++) acc1[o] = fmaf(val, We1[(19 + ff) * 16 + o], acc1[o]);
    }
#pragma unroll
    for (int k = 0; k < 64; k++) {                          // agg [35,99)
        float val = agg[k];
#pragma unroll
        for (int o = 0; o < 16; o++) acc1[o] = fmaf(val, We1[(35 + k) * 16 + o], acc1[o]);
    }

    float e1[16];
#pragma unroll
    for (int o = 0; o < 16; o++) e1[o] = tanhf(acc1[o]);

    float e2[8];
#pragma unroll
    for (int o2 = 0; o2 < 8; o2++) {
        float s = be2[o2];
#pragma unroll
        for (int o = 0; o < 16; o++) s = fmaf(e1[o], We2[o * 8 + o2], s);
        e2[o2] = tanhf(s);
    }
    float s3 = be3[0];
#pragma unroll
    for (int o2 = 0; o2 < 8; o2++) s3 = fmaf(e2[o2], We3[o2], s3);
    out[b * (3 * DD) + t] = s3;
}

// ---------------- launch ---------------------------------------------------
extern "C" void kernel_launch(void* const* d_in, const int* in_sizes, int n_in,
                              void* d_out, int out_size) {
    const float* x      = (const float*)d_in[0];
    const int*   agent  = (const int*)  d_in[1];
    const int*   nbr    = (const int*)  d_in[2];
    const float* Wl     = (const float*)d_in[3];
    const float* Wr     = (const float*)d_in[4];
    const float* attw   = (const float*)d_in[5];
    const float* bias   = (const float*)d_in[6];
    const float* Wg1    = (const float*)d_in[7];
    const float* bg1    = (const float*)d_in[8];
    const float* Wg2    = (const float*)d_in[9];
    const float* bg2    = (const float*)d_in[10];
    const float* We1    = (const float*)d_in[11];
    const float* be1    = (const float*)d_in[12];
    const float* We2    = (const float*)d_in[13];
    const float* be2    = (const float*)d_in[14];
    const float* We3    = (const float*)d_in[15];
    const float* be3    = (const float*)d_in[16];
    float* out = (float*)d_out;

    // layer-0 projections (with fused CSR degree count + pool zeroing)
    proj0_kernel<<<NT / 64, 256>>>(x, (const float*)nbr, Wl, Wr);
    scan_kernel<<<1, 1024>>>();
    fill_kernel<<<(NE + 255) / 256, 256>>>(nbr);

    // 4 fused GATv2 layers (buffers ping-pong A->B->A->B), 1 node/block,
    // 2 rows per thread; last layer also accumulates the pool sums
    gat4_kernel<0, false><<<NB, 128>>>(attw,      bias,      Wl + 256, Wr + 256);
    gat4_kernel<1, false><<<NB, 128>>>(attw + 16, bias + 16, Wl + 512, Wr + 512);
    gat4_kernel<0, false><<<NB, 128>>>(attw + 32, bias + 32, Wl + 768, Wr + 768);
    gat4_kernel<1, true ><<<NB, 128>>>(attw + 48, bias + 48, nullptr,  nullptr);

    // agg-MLP + scorer fused (one block per batch)
    pool2_scorer_kernel<<<BB, 128>>>(agent, nbr, Wg1, bg1, Wg2, bg2,
                                     We1, be1, We2, be2, We3, be3, out);
}

// round 14
// speedup vs baseline: 2.3779x; 2.3779x over previous
#include <cuda_runtime.h>
#include <cuda_fp16.h>
#include <math.h>

#define NB 8192
#define BB 64
#define DD 5
#define NE (NB*DD)      // 40960 neighbor edges
#define NT (NB*BB)      // 524288 (node, batch) rows
#define HC 16

// ---------------- device scratch (no runtime allocation allowed) ------------
__device__ __half g_xlA[(size_t)NT * HC];   // 16.8 MB, layout (n,b,hc) fp16
__device__ __half g_xrA[(size_t)NT * HC];
__device__ __half g_xlB[(size_t)NT * HC];
__device__ __half g_xrB[(size_t)NT * HC];
__device__ float  g_h  [(size_t)NT * HC];   // final-layer h only (fp32)
__device__ float  g_poolp[8 * BB * HC];     // pool partials (chunk, b, f)
__device__ int    g_cnt[NB];                // static zero-init; scan re-zeroes
__device__ int    g_off[NB + 1];
__device__ int    g_cur[NB];
__device__ int    g_csr[NE];

// ---------------- fp16 quarter-row <-> fp32 helpers ------------------------
__device__ __forceinline__ float4 q_h2f(uint2 u) {
    float2 f0 = __half22float2(*reinterpret_cast<__half2*>(&u.x));
    float2 f1 = __half22float2(*reinterpret_cast<__half2*>(&u.y));
    return make_float4(f0.x, f0.y, f1.x, f1.y);
}
__device__ __forceinline__ uint2 q_f2h(float4 v) {
    __half2 h0 = __floats2half2_rn(v.x, v.y);
    __half2 h1 = __floats2half2_rn(v.z, v.w);
    uint2 u;
    u.x = *reinterpret_cast<unsigned*>(&h0);
    u.y = *reinterpret_cast<unsigned*>(&h1);
    return u;
}

// ---------------- CSR scan (re-zeroes counts for next graph replay) --------
__global__ void scan_kernel() {
    __shared__ int wsum[32];
    int t = threadIdx.x;
    int v[8];
    int s = 0;
#pragma unroll
    for (int i = 0; i < 8; i++) {
        v[i] = g_cnt[t * 8 + i];
        g_cnt[t * 8 + i] = 0;          // reset for next replay
        s += v[i];
    }
    unsigned lane = t & 31, wid = t >> 5;
    int x = s;
#pragma unroll
    for (int o = 1; o < 32; o <<= 1) {
        int y = __shfl_up_sync(0xffffffffu, x, o);
        if (lane >= (unsigned)o) x += y;
    }
    if (lane == 31) wsum[wid] = x;
    __syncthreads();
    if (wid == 0) {
        int w = wsum[lane];
#pragma unroll
        for (int o = 1; o < 32; o <<= 1) {
            int y = __shfl_up_sync(0xffffffffu, w, o);
            if (lane >= (unsigned)o) w += y;
        }
        wsum[lane] = w;
    }
    __syncthreads();
    int excl = x - s + (wid ? wsum[wid - 1] : 0);
    int run = excl;
#pragma unroll
    for (int i = 0; i < 8; i++) {
        g_off[t * 8 + i] = run;
        g_cur[t * 8 + i] = run;
        run += v[i];
    }
    if (t == 1023) g_off[NB] = run;
}

__global__ void fill_kernel(const int* __restrict__ neighbors) {
    int e = blockIdx.x * blockDim.x + threadIdx.x;
    if (e < NE) {
        int dst = neighbors[e];
        int pos = atomicAdd(&g_cur[dst], 1);
        g_csr[pos] = e / DD;   // source node of edge e
    }
}

// ---------------- layer-0 projections (quad-sliced, coalesced, fp16 out) ---
__global__ __launch_bounds__(256)
void proj0_kernel(const float* __restrict__ xin,
                  const float* __restrict__ neighbors_i,
                  const float* __restrict__ Wl, const float* __restrict__ Wr) {
    __shared__ float sWl[256], sWr[256];
    int t = threadIdx.x;
    sWl[t] = Wl[t];
    sWr[t] = Wr[t];

    // fused CSR count
    int e = blockIdx.x * 256 + t;
    if (e < NE) atomicAdd(&g_cnt[((const int*)neighbors_i)[e]], 1);
    __syncthreads();

    int row = blockIdx.x * 64 + (t >> 2);   // row = n*64 + b
    int hq  = t & 3;
    int n = row >> 6, b = row & 63;

    float4 xq = __ldcs((const float4*)(xin + ((size_t)b * NB + n) * HC) + hq);

    float4 ol  = make_float4(0.f, 0.f, 0.f, 0.f);
    float4 orr = ol;
    int qbase = (t & 31) & ~3;
#pragma unroll
    for (int f = 0; f < 16; f++) {
        float src = (f & 3) == 0 ? xq.x : (f & 3) == 1 ? xq.y
                  : (f & 3) == 2 ? xq.z : xq.w;
        float hf = __shfl_sync(0xffffffffu, src, qbase | (f >> 2), 32);
        float4 wl = *(const float4*)&sWl[f * 16 + hq * 4];
        float4 wr = *(const float4*)&sWr[f * 16 + hq * 4];
        ol.x  = fmaf(hf, wl.x, ol.x);  ol.y  = fmaf(hf, wl.y, ol.y);
        ol.z  = fmaf(hf, wl.z, ol.z);  ol.w  = fmaf(hf, wl.w, ol.w);
        orr.x = fmaf(hf, wr.x, orr.x); orr.y = fmaf(hf, wr.y, orr.y);
        orr.z = fmaf(hf, wr.z, orr.z); orr.w = fmaf(hf, wr.w, orr.w);
    }
    ((uint2*)(g_xlA + (size_t)row * HC))[hq] = q_f2h(ol);
    ((uint2*)(g_xrA + (size_t)row * HC))[hq] = q_f2h(orr);
}

// ---------------- fused GATv2 layer: 2 rows/thread, head-sliced, fp16 ------
// Block = one node n, 128 threads = 32 batch-pairs x 4 head-quarters.
// Thread (b0 = t>>2, hq = t&3) handles batches b0 and b0+32. Gather
// prefetches issue FIRST so their L2 latency overlaps the prologue math.
template <int IN, bool LAST>
__global__ __launch_bounds__(128)
void gat4_kernel(const float* __restrict__ attw,
                 const float* __restrict__ bias,
                 const float* __restrict__ Wln,   // next layer's Wl (null if LAST)
                 const float* __restrict__ Wrn) { // next layer's Wr (null if LAST)
    __shared__ float sWl[256], sWr[256];
    int t = threadIdx.x;

    const __half* __restrict__ xlin  = (IN == 0) ? g_xlA : g_xlB;
    const __half* __restrict__ xrin  = (IN == 0) ? g_xrA : g_xrB;
    __half*       __restrict__ xlout = (IN == 0) ? g_xlB : g_xlA;
    __half*       __restrict__ xrout = (IN == 0) ? g_xrB : g_xrA;

    int n  = blockIdx.x;
    int b0 = t >> 2;           // 0..31
    int hq = t & 3;
    size_t idx0 = (size_t)n * BB + b0;     // row A
    size_t idx1 = idx0 + 32;               // row B (b0+32)

    // ---- issue gather prefetches as early as possible ---------------------
    int beg = __ldg(&g_off[n]), end = __ldg(&g_off[n + 1]);
    int offA = b0 * HC + hq * 4;           // half units
    int offB = offA + 32 * HC;
    uint2 PA0 = make_uint2(0u, 0u), PB0 = PA0, PA1 = PA0, PB1 = PA0;
    if (beg < end) {
        const __half* p = xlin + (size_t)__ldg(&g_csr[beg]) * (BB * HC);
        PA0 = *(const uint2*)(p + offA);
        PB0 = *(const uint2*)(p + offB);
    }
    if (beg + 1 < end) {
        const __half* p = xlin + (size_t)__ldg(&g_csr[beg + 1]) * (BB * HC);
        PA1 = *(const uint2*)(p + offA);
        PB1 = *(const uint2*)(p + offB);
    }

    // ---- stage next-layer weights (overlaps with prefetch latency) --------
    if (!LAST) {
        sWl[t] = Wln[t]; sWl[t + 128] = Wln[t + 128];
        sWr[t] = Wrn[t]; sWr[t + 128] = Wrn[t + 128];
    }

    const float LOG2E = 1.4426950408889634f;
    float4 att4 = __ldg((const float4*)attw + hq);
    att4.x *= LOG2E; att4.y *= LOG2E; att4.z *= LOG2E; att4.w *= LOG2E;

    float4 xrA = q_h2f(((const uint2*)(xrin + idx0 * HC))[hq]);
    float4 xrB = q_h2f(((const uint2*)(xrin + idx1 * HC))[hq]);

    // ---- self edges -------------------------------------------------------
    float sA, sB;
    float4 accA, accB;
    {
        float4 v = q_h2f(((const uint2*)(xlin + idx0 * HC))[hq]);
        float z, l;
        z = v.x + xrA.x; l  = fmaxf(z, 0.2f * z) * att4.x;
        z = v.y + xrA.y; l += fmaxf(z, 0.2f * z) * att4.y;
        z = v.z + xrA.z; l += fmaxf(z, 0.2f * z) * att4.z;
        z = v.w + xrA.w; l += fmaxf(z, 0.2f * z) * att4.w;
        float w = exp2f(l);
        sA = w;
        accA = make_float4(w * v.x, w * v.y, w * v.z, w * v.w);
    }
    {
        float4 v = q_h2f(((const uint2*)(xlin + idx1 * HC))[hq]);
        float z, l;
        z = v.x + xrB.x; l  = fmaxf(z, 0.2f * z) * att4.x;
        z = v.y + xrB.y; l += fmaxf(z, 0.2f * z) * att4.y;
        z = v.z + xrB.z; l += fmaxf(z, 0.2f * z) * att4.z;
        z = v.w + xrB.w; l += fmaxf(z, 0.2f * z) * att4.w;
        float w = exp2f(l);
        sB = w;
        accB = make_float4(w * v.x, w * v.y, w * v.z, w * v.w);
    }

    // ---- incoming-edge loop, both rows, 2-deep prefetch -------------------
    for (int e = beg; e < end; e++) {
        float4 QA = q_h2f(PA0);
        float4 QB = q_h2f(PB0);
        PA0 = PA1; PB0 = PB1;
        if (e + 2 < end) {
            const __half* p = xlin + (size_t)__ldg(&g_csr[e + 2]) * (BB * HC);
            PA1 = *(const uint2*)(p + offA);
            PB1 = *(const uint2*)(p + offB);
        }
        float z, l;
        z = QA.x + xrA.x; l  = fmaxf(z, 0.2f * z) * att4.x;
        z = QA.y + xrA.y; l += fmaxf(z, 0.2f * z) * att4.y;
        z = QA.z + xrA.z; l += fmaxf(z, 0.2f * z) * att4.z;
        z = QA.w + xrA.w; l += fmaxf(z, 0.2f * z) * att4.w;
        float wA = exp2f(l);
        sA += wA;
        accA.x = fmaf(wA, QA.x, accA.x);
        accA.y = fmaf(wA, QA.y, accA.y);
        accA.z = fmaf(wA, QA.z, accA.z);
        accA.w = fmaf(wA, QA.w, accA.w);

        z = QB.x + xrB.x; l  = fmaxf(z, 0.2f * z) * att4.x;
        z = QB.y + xrB.y; l += fmaxf(z, 0.2f * z) * att4.y;
        z = QB.z + xrB.z; l += fmaxf(z, 0.2f * z) * att4.z;
        z = QB.w + xrB.w; l += fmaxf(z, 0.2f * z) * att4.w;
        float wB = exp2f(l);
        sB += wB;
        accB.x = fmaf(wB, QB.x, accB.x);
        accB.y = fmaf(wB, QB.y, accB.y);
        accB.z = fmaf(wB, QB.z, accB.z);
        accB.w = fmaf(wB, QB.w, accB.w);
    }

    // ---- finalize both new h quarters -------------------------------------
    float4 bb4 = __ldg((const float4*)bias + hq);
    float invA = 1.f / (sA + 1e-16f);
    float invB = 1.f / (sB + 1e-16f);
    float4 oA = make_float4(accA.x * invA + bb4.x, accA.y * invA + bb4.y,
                            accA.z * invA + bb4.z, accA.w * invA + bb4.w);
    float4 oB = make_float4(accB.x * invB + bb4.x, accB.y * invB + bb4.y,
                            accB.z * invB + bb4.z, accB.w * invB + bb4.w);

    if (LAST) {
        ((float4*)(g_h + idx0 * HC))[hq] = oA;
        ((float4*)(g_h + idx1 * HC))[hq] = oB;
        return;
    }

    __syncthreads();                       // weights staged

    // ---- next-layer projections: quad shuffle, weights shared by 2 rows ---
    float4 olA = make_float4(0.f, 0.f, 0.f, 0.f), orA = olA;
    float4 olB = olA, orB = olA;
    int qbase = (t & 31) & ~3;
#pragma unroll
    for (int f = 0; f < 16; f++) {
        float srcA = (f & 3) == 0 ? oA.x : (f & 3) == 1 ? oA.y
                   : (f & 3) == 2 ? oA.z : oA.w;
        float srcB = (f & 3) == 0 ? oB.x : (f & 3) == 1 ? oB.y
                   : (f & 3) == 2 ? oB.z : oB.w;
        float hfA = __shfl_sync(0xffffffffu, srcA, qbase | (f >> 2), 32);
        float hfB = __shfl_sync(0xffffffffu, srcB, qbase | (f >> 2), 32);
        float4 wl = *(const float4*)&sWl[f * 16 + hq * 4];
        float4 wr = *(const float4*)&sWr[f * 16 + hq * 4];
        olA.x = fmaf(hfA, wl.x, olA.x); olA.y = fmaf(hfA, wl.y, olA.y);
        olA.z = fmaf(hfA, wl.z, olA.z); olA.w = fmaf(hfA, wl.w, olA.w);
        orA.x = fmaf(hfA, wr.x, orA.x); orA.y = fmaf(hfA, wr.y, orA.y);
        orA.z = fmaf(hfA, wr.z, orA.z); orA.w = fmaf(hfA, wr.w, orA.w);
        olB.x = fmaf(hfB, wl.x, olB.x); olB.y = fmaf(hfB, wl.y, olB.y);
        olB.z = fmaf(hfB, wl.z, olB.z); olB.w = fmaf(hfB, wl.w, olB.w);
        orB.x = fmaf(hfB, wr.x, orB.x); orB.y = fmaf(hfB, wr.y, orB.y);
        orB.z = fmaf(hfB, wr.z, orB.z); orB.w = fmaf(hfB, wr.w, orB.w);
    }
    ((uint2*)(xlout + idx0 * HC))[hq] = q_f2h(olA);
    ((uint2*)(xrout + idx0 * HC))[hq] = q_f2h(orA);
    ((uint2*)(xlout + idx1 * HC))[hq] = q_f2h(olB);
    ((uint2*)(xrout + idx1 * HC))[hq] = q_f2h(orB);
}

// ---------------- mean-pool over nodes (phase 1: partial sums) -------------
__global__ __launch_bounds__(256)
void pool1_kernel() {
    int b = blockIdx.x >> 3;       // 64 batches
    int chunk = blockIdx.x & 7;    // 8 node chunks of 1024
    int t = threadIdx.x;
    int f = t & 15, g = t >> 4;    // 16 groups
    float sum = 0.f;
    int n0 = chunk * 1024 + g;
    for (int k = 0; k < 64; k++) {
        int n = n0 + k * 16;
        sum += g_h[((size_t)n * BB + b) * HC + f];
    }
    __shared__ float red[256];
    red[t] = sum;
    __syncthreads();
    for (int st = 128; st >= 16; st >>= 1) {
        if (t < st) red[t] += red[t + st];
        __syncthreads();
    }
    if (t < 16) g_poolp[chunk * (BB * HC) + b * HC + t] = red[t];
}

// ---------------- agg MLP + edge scorer, one block per batch ---------------
__global__ __launch_bounds__(128)
void pool2_scorer_kernel(const int* __restrict__ agent_nodes,
                         const int* __restrict__ neighbors,
                         const float* __restrict__ Wg1, const float* __restrict__ bg1,
                         const float* __restrict__ Wg2, const float* __restrict__ bg2,
                         const float* __restrict__ We1, const float* __restrict__ be1,
                         const float* __restrict__ We2, const float* __restrict__ be2,
                         const float* __restrict__ We3, const float* __restrict__ be3,
                         float* __restrict__ out) {
    int b = blockIdx.x;
    int t = threadIdx.x;   // 128 threads
    __shared__ float pool[16], g1[32], agg[64];
    if (t < 16) {
        float s = 0.f;
#pragma unroll
        for (int c = 0; c < 8; c++) s += g_poolp[c * (BB * HC) + b * HC + t];
        pool[t] = s * (1.f / (float)NB);
    }
    __syncthreads();
    if (t < 32) {
        float s = bg1[t];
#pragma unroll
        for (int ff = 0; ff < 16; ff++) s = fmaf(pool[ff], Wg1[ff * 32 + t], s);
        g1[t] = tanhf(s);
    }
    __syncthreads();
    if (t < 64) {
        float s = bg2[t];
#pragma unroll
        for (int k = 0; k < 32; k++) s = fmaf(g1[k], Wg2[k * 64 + t], s);
        agg[t] = tanhf(s);
    }
    __syncthreads();

    if (t >= 3 * DD) return;          // 15 scorer items per batch
    int tk = t / DD;
    int d  = t % DD;
    int an = agent_nodes[b];
    int tg = neighbors[an * DD + d];

    float acc1[16];
#pragma unroll
    for (int o = 0; o < 16; o++) acc1[o] = be1[o];

#pragma unroll
    for (int ff = 0; ff < 16; ff++) {                       // source [0,16)
        float val = g_h[((size_t)an * BB + b) * HC + ff];
#pragma unroll
        for (int o = 0; o < 16; o++) acc1[o] = fmaf(val, We1[ff * 16 + o], acc1[o]);
    }
    {                                                       // token one-hot [16,19)
        int i = 16 + tk;
#pragma unroll
        for (int o = 0; o < 16; o++) acc1[o] += We1[i * 16 + o];
    }
#pragma unroll
    for (int ff = 0; ff < 16; ff++) {                       // target [19,35)
        float val = g_h[((size_t)tg * BB + b) * HC + ff];
#pragma unroll
        for (int o = 0; o < 16; o++) acc1[o] = fmaf(val, We1[(19 + ff) * 16 + o], acc1[o]);
    }
#pragma unroll
    for (int k = 0; k < 64; k++) {                          // agg [35,99)
        float val = agg[k];
#pragma unroll
        for (int o = 0; o < 16; o++) acc1[o] = fmaf(val, We1[(35 + k) * 16 + o], acc1[o]);
    }

    float e1[16];
#pragma unroll
    for (int o = 0; o < 16; o++) e1[o] = tanhf(acc1[o]);

    float e2[8];
#pragma unroll
    for (int o2 = 0; o2 < 8; o2++) {
        float s = be2[o2];
#pragma unroll
        for (int o = 0; o < 16; o++) s = fmaf(e1[o], We2[o * 8 + o2], s);
        e2[o2] = tanhf(s);
    }
    float s3 = be3[0];
#pragma unroll
    for (int o2 = 0; o2 < 8; o2++) s3 = fmaf(e2[o2], We3[o2], s3);
    out[b * (3 * DD) + t] = s3;
}

// ---------------- launch ---------------------------------------------------
extern "C" void kernel_launch(void* const* d_in, const int* in_sizes, int n_in,
                              void* d_out, int out_size) {
    const float* x      = (const float*)d_in[0];
    const int*   agent  = (const int*)  d_in[1];
    const int*   nbr    = (const int*)  d_in[2];
    const float* Wl     = (const float*)d_in[3];
    const float* Wr     = (const float*)d_in[4];
    const float* attw   = (const float*)d_in[5];
    const float* bias   = (const float*)d_in[6];
    const float* Wg1    = (const float*)d_in[7];
    const float* bg1    = (const float*)d_in[8];
    const float* Wg2    = (const float*)d_in[9];
    const float* bg2    = (const float*)d_in[10];
    const float* We1    = (const float*)d_in[11];
    const float* be1    = (const float*)d_in[12];
    const float* We2    = (const float*)d_in[13];
    const float* be2    = (const float*)d_in[14];
    const float* We3    = (const float*)d_in[15];
    const float* be3    = (const float*)d_in[16];
    float* out = (float*)d_out;

    // layer-0 projections (with fused CSR degree count)
    proj0_kernel<<<NT / 64, 256>>>(x, (const float*)nbr, Wl, Wr);
    scan_kernel<<<1, 1024>>>();
    fill_kernel<<<(NE + 255) / 256, 256>>>(nbr);

    // 4 fused GATv2 layers (buffers ping-pong A->B->A->B), 1 node/block,
    // 2 rows per thread
    gat4_kernel<0, false><<<NB, 128>>>(attw,      bias,      Wl + 256, Wr + 256);
    gat4_kernel<1, false><<<NB, 128>>>(attw + 16, bias + 16, Wl + 512, Wr + 512);
    gat4_kernel<0, false><<<NB, 128>>>(attw + 32, bias + 32, Wl + 768, Wr + 768);
    gat4_kernel<1, true ><<<NB, 128>>>(attw + 48, bias + 48, nullptr,  nullptr);

    // pooling partials, then agg-MLP + scorer fused (one block per batch)
    pool1_kernel<<<BB * 8, 256>>>();
    pool2_scorer_kernel<<<BB, 128>>>(agent, nbr, Wg1, bg1, Wg2, bg2,
                                     We1, be1, We2, be2, We3, be3, out);
}

// round 15
// speedup vs baseline: 2.3979x; 1.0084x over previous
#include <cuda_runtime.h>
#include <cuda_fp16.h>
#include <math.h>

#define NB 8192
#define BB 64
#define DD 5
#define NE (NB*DD)      // 40960 neighbor edges
#define NT (NB*BB)      // 524288 (node, batch) rows
#define HC 16

// ---------------- device scratch (no runtime allocation allowed) ------------
__device__ __half g_xlA[(size_t)NT * HC];   // 16.8 MB, layout (n,b,hc) fp16
__device__ __half g_xrA[(size_t)NT * HC];
__device__ __half g_xlB[(size_t)NT * HC];
__device__ __half g_xrB[(size_t)NT * HC];
__device__ float  g_h  [(size_t)NT * HC];   // final-layer h only (fp32)
__device__ float  g_poolp[8 * BB * HC];     // pool partials (chunk, b, f)
__device__ int    g_cnt[NB];                // static zero-init; scan re-zeroes
__device__ int    g_off[NB + 1];
__device__ int    g_cur[NB];
__device__ int    g_csr[NE];

// ---------------- fp16 quarter-row <-> fp32 helpers ------------------------
__device__ __forceinline__ float4 q_h2f(uint2 u) {
    float2 f0 = __half22float2(*reinterpret_cast<__half2*>(&u.x));
    float2 f1 = __half22float2(*reinterpret_cast<__half2*>(&u.y));
    return make_float4(f0.x, f0.y, f1.x, f1.y);
}
__device__ __forceinline__ uint2 q_f2h(float4 v) {
    __half2 h0 = __floats2half2_rn(v.x, v.y);
    __half2 h1 = __floats2half2_rn(v.z, v.w);
    uint2 u;
    u.x = *reinterpret_cast<unsigned*>(&h0);
    u.y = *reinterpret_cast<unsigned*>(&h1);
    return u;
}

// ---------------- CSR scan (re-zeroes counts for next graph replay) --------
__global__ void scan_kernel() {
    __shared__ int wsum[32];
    int t = threadIdx.x;
    int v[8];
    int s = 0;
#pragma unroll
    for (int i = 0; i < 8; i++) {
        v[i] = g_cnt[t * 8 + i];
        g_cnt[t * 8 + i] = 0;          // reset for next replay
        s += v[i];
    }
    unsigned lane = t & 31, wid = t >> 5;
    int x = s;
#pragma unroll
    for (int o = 1; o < 32; o <<= 1) {
        int y = __shfl_up_sync(0xffffffffu, x, o);
        if (lane >= (unsigned)o) x += y;
    }
    if (lane == 31) wsum[wid] = x;
    __syncthreads();
    if (wid == 0) {
        int w = wsum[lane];
#pragma unroll
        for (int o = 1; o < 32; o <<= 1) {
            int y = __shfl_up_sync(0xffffffffu, w, o);
            if (lane >= (unsigned)o) w += y;
        }
        wsum[lane] = w;
    }
    __syncthreads();
    int excl = x - s + (wid ? wsum[wid - 1] : 0);
    int run = excl;
#pragma unroll
    for (int i = 0; i < 8; i++) {
        g_off[t * 8 + i] = run;
        g_cur[t * 8 + i] = run;
        run += v[i];
    }
    if (t == 1023) g_off[NB] = run;
}

__global__ void fill_kernel(const int* __restrict__ neighbors) {
    int e = blockIdx.x * blockDim.x + threadIdx.x;
    if (e < NE) {
        int dst = neighbors[e];
        int pos = atomicAdd(&g_cur[dst], 1);
        g_csr[pos] = e / DD;   // source node of edge e
    }
}

// ---------------- layer-0 projections (quad-sliced, coalesced, fp16 out) ---
__global__ __launch_bounds__(256)
void proj0_kernel(const float* __restrict__ xin,
                  const float* __restrict__ neighbors_i,
                  const float* __restrict__ Wl, const float* __restrict__ Wr) {
    __shared__ float sWl[256], sWr[256];
    int t = threadIdx.x;
    sWl[t] = Wl[t];
    sWr[t] = Wr[t];

    // fused CSR count
    int e = blockIdx.x * 256 + t;
    if (e < NE) atomicAdd(&g_cnt[((const int*)neighbors_i)[e]], 1);
    __syncthreads();

    int row = blockIdx.x * 64 + (t >> 2);   // row = n*64 + b
    int hq  = t & 3;
    int n = row >> 6, b = row & 63;

    float4 xq = __ldcs((const float4*)(xin + ((size_t)b * NB + n) * HC) + hq);

    float4 ol  = make_float4(0.f, 0.f, 0.f, 0.f);
    float4 orr = ol;
    int qbase = (t & 31) & ~3;
#pragma unroll
    for (int f = 0; f < 16; f++) {
        float src = (f & 3) == 0 ? xq.x : (f & 3) == 1 ? xq.y
                  : (f & 3) == 2 ? xq.z : xq.w;
        float hf = __shfl_sync(0xffffffffu, src, qbase | (f >> 2), 32);
        float4 wl = *(const float4*)&sWl[f * 16 + hq * 4];
        float4 wr = *(const float4*)&sWr[f * 16 + hq * 4];
        ol.x  = fmaf(hf, wl.x, ol.x);  ol.y  = fmaf(hf, wl.y, ol.y);
        ol.z  = fmaf(hf, wl.z, ol.z);  ol.w  = fmaf(hf, wl.w, ol.w);
        orr.x = fmaf(hf, wr.x, orr.x); orr.y = fmaf(hf, wr.y, orr.y);
        orr.z = fmaf(hf, wr.z, orr.z); orr.w = fmaf(hf, wr.w, orr.w);
    }
    ((uint2*)(g_xlA + (size_t)row * HC))[hq] = q_f2h(ol);
    ((uint2*)(g_xrA + (size_t)row * HC))[hq] = q_f2h(orr);
}

// ---------------- fused GATv2 layer: 4 rows/thread, head-sliced, fp16 ------
// Block = 2 nodes, 128 threads = 2 x (16 quads). Within a node's 64
// threads: thread (b0 = (t&63)>>2, hq = t&3) handles batches b0, b0+16,
// b0+32, b0+48. Weight LDS + CSR overhead amortized over 4 rows; the 4
// independent row chains give MLP=4 in the edge loop.
template <int IN, bool LAST>
__global__ __launch_bounds__(128)
void gat5_kernel(const float* __restrict__ attw,
                 const float* __restrict__ bias,
                 const float* __restrict__ Wln,   // next layer's Wl (null if LAST)
                 const float* __restrict__ Wrn) { // next layer's Wr (null if LAST)
    __shared__ float sWl[256], sWr[256];
    int t = threadIdx.x;

    const __half* __restrict__ xlin  = (IN == 0) ? g_xlA : g_xlB;
    const __half* __restrict__ xrin  = (IN == 0) ? g_xrA : g_xrB;
    __half*       __restrict__ xlout = (IN == 0) ? g_xlB : g_xlA;
    __half*       __restrict__ xrout = (IN == 0) ? g_xrB : g_xrA;

    int n  = blockIdx.x * 2 + (t >> 6);
    int t64 = t & 63;
    int b0 = t64 >> 2;         // 0..15
    int hq = t & 3;
    size_t base = (size_t)n * BB;
    int off0 = b0 * HC + hq * 4;           // half units; rows r at +16r*HC

    // ---- issue gather prefetches as early as possible ---------------------
    int beg = __ldg(&g_off[n]), end = __ldg(&g_off[n + 1]);
    uint2 P0[4], P1[4];
#pragma unroll
    for (int r = 0; r < 4; r++) { P0[r] = make_uint2(0u, 0u); P1[r] = P0[r]; }
    if (beg < end) {
        const __half* p = xlin + (size_t)__ldg(&g_csr[beg]) * (BB * HC) + off0;
#pragma unroll
        for (int r = 0; r < 4; r++) P0[r] = *(const uint2*)(p + r * 16 * HC);
    }
    if (beg + 1 < end) {
        const __half* p = xlin + (size_t)__ldg(&g_csr[beg + 1]) * (BB * HC) + off0;
#pragma unroll
        for (int r = 0; r < 4; r++) P1[r] = *(const uint2*)(p + r * 16 * HC);
    }

    // ---- stage next-layer weights (overlaps with prefetch latency) --------
    if (!LAST) {
        sWl[t] = Wln[t]; sWl[t + 128] = Wln[t + 128];
        sWr[t] = Wrn[t]; sWr[t + 128] = Wrn[t + 128];
    }

    const float LOG2E = 1.4426950408889634f;
    float4 att4 = __ldg((const float4*)attw + hq);
    att4.x *= LOG2E; att4.y *= LOG2E; att4.z *= LOG2E; att4.w *= LOG2E;

    float4 xr4[4];
#pragma unroll
    for (int r = 0; r < 4; r++)
        xr4[r] = q_h2f(*(const uint2*)(xrin + (base + b0 + 16 * r) * HC + hq * 4));

    // ---- self edges -------------------------------------------------------
    float s[4];
    float4 acc[4];
#pragma unroll
    for (int r = 0; r < 4; r++) {
        float4 v = q_h2f(*(const uint2*)(xlin + (base + b0 + 16 * r) * HC + hq * 4));
        float z, l;
        z = v.x + xr4[r].x; l  = fmaxf(z, 0.2f * z) * att4.x;
        z = v.y + xr4[r].y; l += fmaxf(z, 0.2f * z) * att4.y;
        z = v.z + xr4[r].z; l += fmaxf(z, 0.2f * z) * att4.z;
        z = v.w + xr4[r].w; l += fmaxf(z, 0.2f * z) * att4.w;
        float w = exp2f(l);
        s[r] = w;
        acc[r] = make_float4(w * v.x, w * v.y, w * v.z, w * v.w);
    }

    // ---- incoming-edge loop, 4 rows, 2-deep prefetch ----------------------
    for (int e = beg; e < end; e++) {
        float4 Q[4];
#pragma unroll
        for (int r = 0; r < 4; r++) { Q[r] = q_h2f(P0[r]); P0[r] = P1[r]; }
        if (e + 2 < end) {
            const __half* p = xlin + (size_t)__ldg(&g_csr[e + 2]) * (BB * HC) + off0;
#pragma unroll
            for (int r = 0; r < 4; r++) P1[r] = *(const uint2*)(p + r * 16 * HC);
        }
#pragma unroll
        for (int r = 0; r < 4; r++) {
            float z, l;
            z = Q[r].x + xr4[r].x; l  = fmaxf(z, 0.2f * z) * att4.x;
            z = Q[r].y + xr4[r].y; l += fmaxf(z, 0.2f * z) * att4.y;
            z = Q[r].z + xr4[r].z; l += fmaxf(z, 0.2f * z) * att4.z;
            z = Q[r].w + xr4[r].w; l += fmaxf(z, 0.2f * z) * att4.w;
            float w = exp2f(l);
            s[r] += w;
            acc[r].x = fmaf(w, Q[r].x, acc[r].x);
            acc[r].y = fmaf(w, Q[r].y, acc[r].y);
            acc[r].z = fmaf(w, Q[r].z, acc[r].z);
            acc[r].w = fmaf(w, Q[r].w, acc[r].w);
        }
    }

    // ---- finalize the 4 new h quarters -------------------------------------
    float4 bb4 = __ldg((const float4*)bias + hq);
    float4 o4[4];
#pragma unroll
    for (int r = 0; r < 4; r++) {
        float inv = 1.f / (s[r] + 1e-16f);
        o4[r] = make_float4(acc[r].x * inv + bb4.x, acc[r].y * inv + bb4.y,
                            acc[r].z * inv + bb4.z, acc[r].w * inv + bb4.w);
    }

    if (LAST) {
#pragma unroll
        for (int r = 0; r < 4; r++)
            *(float4*)(g_h + (base + b0 + 16 * r) * HC + hq * 4) = o4[r];
        return;
    }

    __syncthreads();                       // weights staged

    // ---- next-layer projections: quad shuffle, weights shared by 4 rows ---
    float4 ol[4], orr[4];
#pragma unroll
    for (int r = 0; r < 4; r++) {
        ol[r] = make_float4(0.f, 0.f, 0.f, 0.f);
        orr[r] = ol[r];
    }
    int qbase = (t & 31) & ~3;
#pragma unroll
    for (int f = 0; f < 16; f++) {
        float4 wl = *(const float4*)&sWl[f * 16 + hq * 4];
        float4 wr = *(const float4*)&sWr[f * 16 + hq * 4];
#pragma unroll
        for (int r = 0; r < 4; r++) {
            float src = (f & 3) == 0 ? o4[r].x : (f & 3) == 1 ? o4[r].y
                      : (f & 3) == 2 ? o4[r].z : o4[r].w;
            float hf = __shfl_sync(0xffffffffu, src, qbase | (f >> 2), 32);
            ol[r].x  = fmaf(hf, wl.x, ol[r].x);  ol[r].y  = fmaf(hf, wl.y, ol[r].y);
            ol[r].z  = fmaf(hf, wl.z, ol[r].z);  ol[r].w  = fmaf(hf, wl.w, ol[r].w);
            orr[r].x = fmaf(hf, wr.x, orr[r].x); orr[r].y = fmaf(hf, wr.y, orr[r].y);
            orr[r].z = fmaf(hf, wr.z, orr[r].z); orr[r].w = fmaf(hf, wr.w, orr[r].w);
        }
    }
#pragma unroll
    for (int r = 0; r < 4; r++) {
        size_t idx = base + b0 + 16 * r;
        *(uint2*)(xlout + idx * HC + hq * 4) = q_f2h(ol[r]);
        *(uint2*)(xrout + idx * HC + hq * 4) = q_f2h(orr[r]);
    }
}

// ---------------- mean-pool over nodes (phase 1: partial sums) -------------
__global__ __launch_bounds__(256)
void pool1_kernel() {
    int b = blockIdx.x >> 3;       // 64 batches
    int chunk = blockIdx.x & 7;    // 8 node chunks of 1024
    int t = threadIdx.x;
    int f = t & 15, g = t >> 4;    // 16 groups
    float sum = 0.f;
    int n0 = chunk * 1024 + g;
    for (int k = 0; k < 64; k++) {
        int n = n0 + k * 16;
        sum += g_h[((size_t)n * BB + b) * HC + f];
    }
    __shared__ float red[256];
    red[t] = sum;
    __syncthreads();
    for (int st = 128; st >= 16; st >>= 1) {
        if (t < st) red[t] += red[t + st];
        __syncthreads();
    }
    if (t < 16) g_poolp[chunk * (BB * HC) + b * HC + t] = red[t];
}

// ---------------- agg MLP + edge scorer, one block per batch ---------------
__global__ __launch_bounds__(128)
void pool2_scorer_kernel(const int* __restrict__ agent_nodes,
                         const int* __restrict__ neighbors,
                         const float* __restrict__ Wg1, const float* __restrict__ bg1,
                         const float* __restrict__ Wg2, const float* __restrict__ bg2,
                         const float* __restrict__ We1, const float* __restrict__ be1,
                         const float* __restrict__ We2, const float* __restrict__ be2,
                         const float* __restrict__ We3, const float* __restrict__ be3,
                         float* __restrict__ out) {
    int b = blockIdx.x;
    int t = threadIdx.x;   // 128 threads
    __shared__ float pool[16], g1[32], agg[64];
    if (t < 16) {
        float s = 0.f;
#pragma unroll
        for (int c = 0; c < 8; c++) s += g_poolp[c * (BB * HC) + b * HC + t];
        pool[t] = s * (1.f / (float)NB);
    }
    __syncthreads();
    if (t < 32) {
        float s = bg1[t];
#pragma unroll
        for (int ff = 0; ff < 16; ff++) s = fmaf(pool[ff], Wg1[ff * 32 + t], s);
        g1[t] = tanhf(s);
    }
    __syncthreads();
    if (t < 64) {
        float s = bg2[t];
#pragma unroll
        for (int k = 0; k < 32; k++) s = fmaf(g1[k], Wg2[k * 64 + t], s);
        agg[t] = tanhf(s);
    }
    __syncthreads();

    if (t >= 3 * DD) return;          // 15 scorer items per batch
    int tk = t / DD;
    int d  = t % DD;
    int an = agent_nodes[b];
    int tg = neighbors[an * DD + d];

    float acc1[16];
#pragma unroll
    for (int o = 0; o < 16; o++) acc1[o] = be1[o];

#pragma unroll
    for (int ff = 0; ff < 16; ff++) {                       // source [0,16)
        float val = g_h[((size_t)an * BB + b) * HC + ff];
#pragma unroll
        for (int o = 0; o < 16; o++) acc1[o] = fmaf(val, We1[ff * 16 + o], acc1[o]);
    }
    {                                                       // token one-hot [16,19)
        int i = 16 + tk;
#pragma unroll
        for (int o = 0; o < 16; o++) acc1[o] += We1[i * 16 + o];
    }
#pragma unroll
    for (int ff = 0; ff < 16; ff++) {                       // target [19,35)
        float val = g_h[((size_t)tg * BB + b) * HC + ff];
#pragma unroll
        for (int o = 0; o < 16; o++) acc1[o] = fmaf(val, We1[(19 + ff) * 16 + o], acc1[o]);
    }
#pragma unroll
    for (int k = 0; k < 64; k++) {                          // agg [35,99)
        float val = agg[k];
#pragma unroll
        for (int o = 0; o < 16; o++) acc1[o] = fmaf(val, We1[(35 + k) * 16 + o], acc1[o]);
    }

    float e1[16];
#pragma unroll
    for (int o = 0; o < 16; o++) e1[o] = tanhf(acc1[o]);

    float e2[8];
#pragma unroll
    for (int o2 = 0; o2 < 8; o2++) {
        float s = be2[o2];
#pragma unroll
        for (int o = 0; o < 16; o++) s = fmaf(e1[o], We2[o * 8 + o2], s);
        e2[o2] = tanhf(s);
    }
    float s3 = be3[0];
#pragma unroll
    for (int o2 = 0; o2 < 8; o2++) s3 = fmaf(e2[o2], We3[o2], s3);
    out[b * (3 * DD) + t] = s3;
}

// ---------------- launch ---------------------------------------------------
extern "C" void kernel_launch(void* const* d_in, const int* in_sizes, int n_in,
                              void* d_out, int out_size) {
    const float* x      = (const float*)d_in[0];
    const int*   agent  = (const int*)  d_in[1];
    const int*   nbr    = (const int*)  d_in[2];
    const float* Wl     = (const float*)d_in[3];
    const float* Wr     = (const float*)d_in[4];
    const float* attw   = (const float*)d_in[5];
    const float* bias   = (const float*)d_in[6];
    const float* Wg1    = (const float*)d_in[7];
    const float* bg1    = (const float*)d_in[8];
    const float* Wg2    = (const float*)d_in[9];
    const float* bg2    = (const float*)d_in[10];
    const float* We1    = (const float*)d_in[11];
    const float* be1    = (const float*)d_in[12];
    const float* We2    = (const float*)d_in[13];
    const float* be2    = (const float*)d_in[14];
    const float* We3    = (const float*)d_in[15];
    const float* be3    = (const float*)d_in[16];
    float* out = (float*)d_out;

    // layer-0 projections (with fused CSR degree count)
    proj0_kernel<<<NT / 64, 256>>>(x, (const float*)nbr, Wl, Wr);
    scan_kernel<<<1, 1024>>>();
    fill_kernel<<<(NE + 255) / 256, 256>>>(nbr);

    // 4 fused GATv2 layers (buffers ping-pong A->B->A->B), 2 nodes/block,
    // 4 rows per thread
    gat5_kernel<0, false><<<NB / 2, 128>>>(attw,      bias,      Wl + 256, Wr + 256);
    gat5_kernel<1, false><<<NB / 2, 128>>>(attw + 16, bias + 16, Wl + 512, Wr + 512);
    gat5_kernel<0, false><<<NB / 2, 128>>>(attw + 32, bias + 32, Wl + 768, Wr + 768);
    gat5_kernel<1, true ><<<NB / 2, 128>>>(attw + 48, bias + 48, nullptr,  nullptr);

    // pooling partials, then agg-MLP + scorer fused (one block per batch)
    pool1_kernel<<<BB * 8, 256>>>();
    pool2_scorer_kernel<<<BB, 128>>>(agent, nbr, Wg1, bg1, Wg2, bg2,
                                     We1, be1, We2, be2, We3, be3, out);
}